// round 7
// baseline (speedup 1.0000x reference)
#include <cuda_runtime.h>
#include <cuda_fp16.h>
#include <cstdint>

// ---------------------------------------------------------------------------
// GRU via mma.sync (HMMA). 128 CTAs x 512 thr, 32 samples/CTA.
// R7: K-split across warp pairs (wid&7 = rows, wid>>3 = K-half) -> 16 warps;
// weights plain fp16 (hi only), h/x carried hi+lo fp16. Partial-sum exchange
// + sample-split epilogue through SMEM.
// ---------------------------------------------------------------------------

#define HID  128
#define MB   32
#define LSEQ 128
#define NCLS 24
#define NTHR 512

// A-fragment arrays: [frag][lane] uint4, frag = mt*nkt + kt
__device__ uint4 g_wih1H[24 * 32], g_wih1L[24 * 32];   // K=16
__device__ uint4 g_whh1H[192 * 32];                    // K=128, streamed
__device__ uint4 g_wih2H[192 * 32];                    // streamed
__device__ uint4 g_whh2H[192 * 32];                    // SMEM-resident

// SMEM byte offsets
#define S_WH2   0        // whh2 hi frags (98304)
#define S_PART  98304    // partial-sum exchange: 8 wpair x 2 dir x 4096
#define S_H1HI  163840   // h tiles: 32x128 fp16 swizzled (8192 each)
#define S_H1LO  172032
#define S_H2HI  180224
#define S_H2LO  188416
#define S_XHI   196608   // x tiles: 32x16 fp16 (1024 each)
#define S_XLO   197632
#define S_BIAS  198656   // 128 x 2 float4 (4096)
#define SMEM_SZ 202752

__device__ __forceinline__ uint32_t smem_u32(const void* p) {
    uint32_t a;
    asm("{ .reg .u64 t; cvta.to.shared.u64 t, %1; cvt.u32.u64 %0, t; }"
        : "=r"(a) : "l"(p));
    return a;
}
__device__ __forceinline__ void ldm2(uint32_t& r0, uint32_t& r1, uint32_t a) {
    asm volatile("ldmatrix.sync.aligned.m8n8.x2.shared.b16 {%0,%1}, [%2];"
                 : "=r"(r0), "=r"(r1) : "r"(a));
}
__device__ __forceinline__ void mmaf(float* d, const uint4& a,
                                     uint32_t b0, uint32_t b1) {
    asm volatile("mma.sync.aligned.m16n8k16.row.col.f32.f16.f16.f32 "
                 "{%0,%1,%2,%3}, {%4,%5,%6,%7}, {%8,%9}, {%0,%1,%2,%3};"
                 : "+f"(d[0]), "+f"(d[1]), "+f"(d[2]), "+f"(d[3])
                 : "r"(a.x), "r"(a.y), "r"(a.z), "r"(a.w), "r"(b0), "r"(b1));
}
__device__ __forceinline__ float sigf(float v) { return 1.f / (1.f + __expf(-v)); }
__device__ __forceinline__ float tanhf_fast(float v) {
    v = fminf(fmaxf(v, -15.f), 15.f);
    float e = __expf(2.f * v);
    return (e - 1.f) / (e + 1.f);
}

// ---- prep: pack fp32 weights into per-lane A fragments --------------------
__global__ void prep_kernel(const float* __restrict__ w_ih1,
                            const float* __restrict__ w_hh1,
                            const float* __restrict__ w_ih2,
                            const float* __restrict__ w_hh2) {
    int t = blockIdx.x * blockDim.x + threadIdx.x;
    if (t >= 600 * 32) return;
    int f = t >> 5, lane = t & 31;
    const float* W; uint4* dh; uint4* dl = nullptr; int K, fl;
    if (f < 24)       { W = w_ih1; dh = g_wih1H; dl = g_wih1L; K = 16;  fl = f; }
    else if (f < 216) { W = w_hh1; dh = g_whh1H; K = 128; fl = f - 24; }
    else if (f < 408) { W = w_ih2; dh = g_wih2H; K = 128; fl = f - 216; }
    else              { W = w_hh2; dh = g_whh2H; K = 128; fl = f - 408; }
    int nkt = K >> 4;
    int mt = fl / nkt, kt = fl % nkt;
    int gid = lane >> 2, tig = lane & 3;
    int r0 = mt * 16 + gid, r1 = r0 + 8, c0 = kt * 16 + tig * 2;
    float2 v[4];
    v[0] = *(const float2*)(W + r0 * K + c0);
    v[1] = *(const float2*)(W + r1 * K + c0);
    v[2] = *(const float2*)(W + r0 * K + c0 + 8);
    v[3] = *(const float2*)(W + r1 * K + c0 + 8);
    uint4 oh, ol;
    uint32_t* ph = (uint32_t*)&oh;
    uint32_t* pl = (uint32_t*)&ol;
#pragma unroll
    for (int q = 0; q < 4; q++) {
        __half2 hi = __floats2half2_rn(v[q].x, v[q].y);
        __half2 lo = __floats2half2_rn(v[q].x - __half2float(__low2half(hi)),
                                       v[q].y - __half2float(__high2half(hi)));
        ph[q] = *(uint32_t*)&hi;
        pl[q] = *(uint32_t*)&lo;
    }
    dh[fl * 32 + lane] = oh;
    if (dl) dl[fl * 32 + lane] = ol;
}

// ---- epilogue: reduce partials + gate math + h hi/lo store ----------------
__device__ __forceinline__ void epilogue(
    float (&ar)[4][4], float (&az)[4][4], float (&ai)[4][4], float (&ah)[4][4],
    int ntb, float* hreg, char* smem, int hiOff, int layer,
    int tig, int gid, int wbase, const float4* rbuf, int lane) {
    float4 v;
#define ADDV(A, r, i) { v = rbuf[(i) * 32 + lane]; \
    A[r][0] += v.x; A[r][1] += v.y; A[r][2] += v.z; A[r][3] += v.w; }
    ADDV(ar, ntb, 0) ADDV(ar, ntb + 1, 1)
    ADDV(az, ntb, 2) ADDV(az, ntb + 1, 3)
    ADDV(ai, ntb, 4) ADDV(ai, ntb + 1, 5)
    ADDV(ah, ntb, 6) ADDV(ah, ntb + 1, 7)
#undef ADDV
    const float4* bt = (const float4*)(smem + S_BIAS);
#pragma unroll
    for (int rowi = 0; rowi < 2; rowi++) {
        int j = wbase + gid + rowi * 8;
        float4 bb = bt[j * 2 + layer];
#pragma unroll
        for (int ntl = 0; ntl < 2; ntl++) {
            int nt = ntb + ntl;
#pragma unroll
            for (int s = 0; s < 2; s++) {
                int e = rowi * 2 + s;
                int m = nt * 8 + tig * 2 + s;
                float r = sigf(ar[nt][e] + bb.x);
                float z = sigf(az[nt][e] + bb.y);
                float n = tanhf_fast(ai[nt][e] + bb.z + r * (ah[nt][e] + bb.w));
                int idx = ntl * 4 + e;
                float h = n + z * (hreg[idx] - n);
                hreg[idx] = h;
                __half hi = __float2half_rn(h);
                __half lo = __float2half_rn(h - __half2float(hi));
                int off = m * 256 + ((2 * j) ^ ((m & 7) << 4));
                *(__half*)(smem + hiOff + off) = hi;
                *(__half*)(smem + hiOff + 8192 + off) = lo;
            }
        }
    }
}

// ---------------------------------------------------------------------------
__global__ __launch_bounds__(NTHR, 1)
void gru_mma_kernel(const float* __restrict__ x,
                    const float* __restrict__ b_ih1, const float* __restrict__ b_hh1,
                    const float* __restrict__ b_ih2, const float* __restrict__ b_hh2,
                    const float* __restrict__ fc_w,  const float* __restrict__ fc_b,
                    float* __restrict__ out) {
    extern __shared__ char smem[];
    const uint32_t sb = smem_u32(smem);
    const int tid = threadIdx.x;
    const int wid = tid >> 5, lane = tid & 31;
    const int khalf = wid >> 3;          // K-half: 0 -> kt 0-3, 1 -> kt 4-7
    const int wpair = wid & 7;           // row-group
    const int b0 = blockIdx.x * MB;
    const int gid = lane >> 2, tig = lane & 3;
    const int lr = lane & 7, lh = (lane >> 3) & 1;
    const int xorv = lr << 4;
    const int wbase = wpair * 16;
    const int ntb = khalf ? 2 : 0;       // nt pair this thread finalizes
    const int nts = khalf ? 0 : 2;       // nt pair sent to partner
    const int kt0 = khalf * 4;

    float4* sbuf = (float4*)(smem + S_PART + wpair * 8192 + khalf * 4096);
    const float4* rbuf = (const float4*)(smem + S_PART + wpair * 8192 + (khalf ^ 1) * 4096);

    // init: whh2 frags -> SMEM, zero h tiles, x(0), bias table
    {
        uint4* d2 = (uint4*)(smem + S_WH2);
        for (int i = tid; i < 192 * 32; i += NTHR) d2[i] = g_whh2H[i];
        uint4 z4 = make_uint4(0, 0, 0, 0);
        uint4* hz = (uint4*)(smem + S_H1HI);
        for (int i = tid; i < 32768 / 16; i += NTHR) hz[i] = z4;
    }
    if (tid < 256) {
        int m = tid >> 3, p = tid & 7;
        const float2 v = *(const float2*)(x + (size_t)(b0 + m) * 2048 +
                                          (p >> 2) * 1024 + ((2 * p) & 7));
        __half2 hi = __floats2half2_rn(v.x, v.y);
        __half2 lo = __floats2half2_rn(v.x - __half2float(__low2half(hi)),
                                       v.y - __half2float(__high2half(hi)));
        *(__half2*)(smem + S_XHI + m * 32 + p * 4) = hi;
        *(__half2*)(smem + S_XLO + m * 32 + p * 4) = lo;
    }
    if (tid < 128) {
        float4* bt = (float4*)(smem + S_BIAS);
        int j = tid;
        bt[j * 2 + 0] = make_float4(b_ih1[j] + b_hh1[j],
                                    b_ih1[128 + j] + b_hh1[128 + j],
                                    b_ih1[256 + j], b_hh1[256 + j]);
        bt[j * 2 + 1] = make_float4(b_ih2[j] + b_hh2[j],
                                    b_ih2[128 + j] + b_hh2[128 + j],
                                    b_ih2[256 + j], b_hh2[256 + j]);
    }

    float h1reg[8], h2reg[8];
#pragma unroll
    for (int q = 0; q < 8; q++) { h1reg[q] = 0.f; h2reg[q] = 0.f; }

    float ar[4][4], az[4][4], ai[4][4], ah[4][4];
    __syncthreads();

#define ZERO_ACC() { _Pragma("unroll") for (int nt = 0; nt < 4; nt++) \
    _Pragma("unroll") for (int e = 0; e < 4; e++) { \
        ar[nt][e] = 0.f; az[nt][e] = 0.f; ai[nt][e] = 0.f; ah[nt][e] = 0.f; } }

#define SEND_PART() { \
    sbuf[0 * 32 + lane] = make_float4(ar[nts][0], ar[nts][1], ar[nts][2], ar[nts][3]); \
    sbuf[1 * 32 + lane] = make_float4(ar[nts+1][0], ar[nts+1][1], ar[nts+1][2], ar[nts+1][3]); \
    sbuf[2 * 32 + lane] = make_float4(az[nts][0], az[nts][1], az[nts][2], az[nts][3]); \
    sbuf[3 * 32 + lane] = make_float4(az[nts+1][0], az[nts+1][1], az[nts+1][2], az[nts+1][3]); \
    sbuf[4 * 32 + lane] = make_float4(ai[nts][0], ai[nts][1], ai[nts][2], ai[nts][3]); \
    sbuf[5 * 32 + lane] = make_float4(ai[nts+1][0], ai[nts+1][1], ai[nts+1][2], ai[nts+1][3]); \
    sbuf[6 * 32 + lane] = make_float4(ah[nts][0], ah[nts][1], ah[nts][2], ah[nts][3]); \
    sbuf[7 * 32 + lane] = make_float4(ah[nts+1][0], ah[nts+1][1], ah[nts+1][2], ah[nts+1][3]); }

#pragma unroll 1
    for (int t = 0; t < LSEQ; t++) {
        ZERO_ACC();
        // ---- L1 ----
        if (khalf) {  // x contribution (K=16, 3-term: Whi*xhi + Whi*xlo + Wlo*xhi)
            uint4 Ar = g_wih1H[wpair * 32 + lane];
            uint4 Az = g_wih1H[(8 + wpair) * 32 + lane];
            uint4 Ai = g_wih1H[(16 + wpair) * 32 + lane];
            uint4 Lr = g_wih1L[wpair * 32 + lane];
            uint4 Lz = g_wih1L[(8 + wpair) * 32 + lane];
            uint4 Li = g_wih1L[(16 + wpair) * 32 + lane];
#pragma unroll
            for (int nt = 0; nt < 4; nt++) {
                uint32_t a = sb + S_XHI + (nt * 8 + lr) * 32 + lh * 16;
                uint32_t bh0, bh1, bl0, bl1;
                ldm2(bh0, bh1, a);
                ldm2(bl0, bl1, a + 1024);
                mmaf(ar[nt], Ar, bh0, bh1); mmaf(ar[nt], Ar, bl0, bl1); mmaf(ar[nt], Lr, bh0, bh1);
                mmaf(az[nt], Az, bh0, bh1); mmaf(az[nt], Az, bl0, bl1); mmaf(az[nt], Lz, bh0, bh1);
                mmaf(ai[nt], Ai, bh0, bh1); mmaf(ai[nt], Ai, bl0, bl1); mmaf(ai[nt], Li, bh0, bh1);
            }
        }
        // whh1 @ h1 (streamed from L2), this warp's K-half
#pragma unroll 2
        for (int kk = 0; kk < 4; kk++) {
            int kt = kt0 + kk;
            uint4 Ar = g_whh1H[(wpair * 8 + kt) * 32 + lane];
            uint4 Az = g_whh1H[((8 + wpair) * 8 + kt) * 32 + lane];
            uint4 An = g_whh1H[((16 + wpair) * 8 + kt) * 32 + lane];
            uint32_t kb = (uint32_t)((kt * 32 + lh * 16) ^ xorv);
#pragma unroll
            for (int nt = 0; nt < 4; nt++) {
                uint32_t a = sb + S_H1HI + (nt * 8 + lr) * 256 + kb;
                uint32_t bh0, bh1, bl0, bl1;
                ldm2(bh0, bh1, a);
                ldm2(bl0, bl1, a + 8192);
                mmaf(ar[nt], Ar, bh0, bh1); mmaf(ar[nt], Ar, bl0, bl1);
                mmaf(az[nt], Az, bh0, bh1); mmaf(az[nt], Az, bl0, bl1);
                mmaf(ah[nt], An, bh0, bh1); mmaf(ah[nt], An, bl0, bl1);
            }
        }
        SEND_PART();
        __syncthreads();                       // partials published, h1 reads done
        epilogue(ar, az, ai, ah, ntb, h1reg, smem, S_H1HI, 0,
                 tig, gid, wbase, rbuf, lane);
        if (!khalf && t + 1 < LSEQ) {          // stage x(t+1) (tid<256 == khalf0)
            int m = tid >> 3, p = tid & 7;
            const float2 v = *(const float2*)(x + (size_t)(b0 + m) * 2048 +
                                              (p >> 2) * 1024 + (t + 1) * 8 + ((2 * p) & 7));
            __half2 hi = __floats2half2_rn(v.x, v.y);
            __half2 lo = __floats2half2_rn(v.x - __half2float(__low2half(hi)),
                                           v.y - __half2float(__high2half(hi)));
            *(__half2*)(smem + S_XHI + m * 32 + p * 4) = hi;
            *(__half2*)(smem + S_XLO + m * 32 + p * 4) = lo;
        }
        __syncthreads();                       // h1(t) visible

        // ---- L2 ----
        ZERO_ACC();
        // wih2 @ h1 (streamed from L2)
#pragma unroll 2
        for (int kk = 0; kk < 4; kk++) {
            int kt = kt0 + kk;
            uint4 Ar = g_wih2H[(wpair * 8 + kt) * 32 + lane];
            uint4 Az = g_wih2H[((8 + wpair) * 8 + kt) * 32 + lane];
            uint4 Ai = g_wih2H[((16 + wpair) * 8 + kt) * 32 + lane];
            uint32_t kb = (uint32_t)((kt * 32 + lh * 16) ^ xorv);
#pragma unroll
            for (int nt = 0; nt < 4; nt++) {
                uint32_t a = sb + S_H1HI + (nt * 8 + lr) * 256 + kb;
                uint32_t bh0, bh1, bl0, bl1;
                ldm2(bh0, bh1, a);
                ldm2(bl0, bl1, a + 8192);
                mmaf(ar[nt], Ar, bh0, bh1); mmaf(ar[nt], Ar, bl0, bl1);
                mmaf(az[nt], Az, bh0, bh1); mmaf(az[nt], Az, bl0, bl1);
                mmaf(ai[nt], Ai, bh0, bh1); mmaf(ai[nt], Ai, bl0, bl1);
            }
        }
        // whh2 @ h2 (SMEM-resident frags)
#pragma unroll 2
        for (int kk = 0; kk < 4; kk++) {
            int kt = kt0 + kk;
            const uint4* wf = (const uint4*)(smem + S_WH2);
            uint4 Ar = wf[(wpair * 8 + kt) * 32 + lane];
            uint4 Az = wf[((8 + wpair) * 8 + kt) * 32 + lane];
            uint4 An = wf[((16 + wpair) * 8 + kt) * 32 + lane];
            uint32_t kb = (uint32_t)((kt * 32 + lh * 16) ^ xorv);
#pragma unroll
            for (int nt = 0; nt < 4; nt++) {
                uint32_t a = sb + S_H2HI + (nt * 8 + lr) * 256 + kb;
                uint32_t bh0, bh1, bl0, bl1;
                ldm2(bh0, bh1, a);
                ldm2(bl0, bl1, a + 8192);
                mmaf(ar[nt], Ar, bh0, bh1); mmaf(ar[nt], Ar, bl0, bl1);
                mmaf(az[nt], Az, bh0, bh1); mmaf(az[nt], Az, bl0, bl1);
                mmaf(ah[nt], An, bh0, bh1); mmaf(ah[nt], An, bl0, bl1);
            }
        }
        SEND_PART();
        __syncthreads();                       // partials published, h reads done
        epilogue(ar, az, ai, ah, ntb, h2reg, smem, S_H2HI, 1,
                 tig, gid, wbase, rbuf, lane);
        __syncthreads();                       // h2(t) + partial buffer free
    }

    // ---- FC head ----
    float* hs = (float*)(smem + S_PART);       // [32][128] fp32
#pragma unroll
    for (int ntl = 0; ntl < 2; ntl++)
#pragma unroll
        for (int rowi = 0; rowi < 2; rowi++)
#pragma unroll
            for (int s = 0; s < 2; s++) {
                int m = (ntb + ntl) * 8 + tig * 2 + s;
                int j = wbase + gid + rowi * 8;
                hs[m * 128 + j] = h2reg[ntl * 4 + rowi * 2 + s];
            }
    __syncthreads();
    if (tid < 256) {
        int o0 = tid * 3;
#pragma unroll
        for (int o = o0; o < o0 + 3; o++) {
            int m = o / NCLS, c = o - (o / NCLS) * NCLS;
            float acc = fc_b[c];
#pragma unroll 4
            for (int k = 0; k < HID; k++)
                acc = fmaf(fc_w[c * HID + k], hs[m * 128 + k], acc);
            out[(size_t)(b0 + m) * NCLS + c] = acc;
        }
    }
}

// ---------------------------------------------------------------------------
extern "C" void kernel_launch(void* const* d_in, const int* in_sizes, int n_in,
                              void* d_out, int out_size) {
    const float* x     = (const float*)d_in[0];
    const float* w_ih1 = (const float*)d_in[1];
    const float* w_hh1 = (const float*)d_in[2];
    const float* b_ih1 = (const float*)d_in[3];
    const float* b_hh1 = (const float*)d_in[4];
    const float* w_ih2 = (const float*)d_in[5];
    const float* w_hh2 = (const float*)d_in[6];
    const float* b_ih2 = (const float*)d_in[7];
    const float* b_hh2 = (const float*)d_in[8];
    const float* fc_w  = (const float*)d_in[9];
    const float* fc_b  = (const float*)d_in[10];
    float* out = (float*)d_out;

    cudaFuncSetAttribute(gru_mma_kernel,
                         cudaFuncAttributeMaxDynamicSharedMemorySize, SMEM_SZ);

    prep_kernel<<<75, 256>>>(w_ih1, w_hh1, w_ih2, w_hh2);
    gru_mma_kernel<<<4096 / MB, NTHR, SMEM_SZ>>>(x, b_ih1, b_hh1, b_ih2, b_hh2,
                                                 fc_w, fc_b, out);
}

// round 8
// speedup vs baseline: 2.5419x; 2.5419x over previous
#include <cuda_runtime.h>
#include <cuda_fp16.h>
#include <cstdint>

// ---------------------------------------------------------------------------
// GRU via mma.sync (HMMA). 128 CTAs x 512 thr (16 warps), 32 samples/CTA.
// R8: sample-split warps — warp (wpair=wid&7, shalf=wid>>3) owns gate rows
// 16*wpair and samples 16*shalf..+15. All work warp-local; the two sample
// halves sync only among themselves via named barriers (bar.sync 1/2, 256).
// Weights fp16 hi-only (whh1+whh2 SMEM-resident, wih2 streamed from L2);
// h and x carried as fp16 hi+lo pairs.
// ---------------------------------------------------------------------------

#define HID  128
#define MB   32
#define LSEQ 128
#define NCLS 24
#define NTHR 512

// A-fragment arrays: [frag][lane] uint4, frag = mt*nkt + kt
__device__ uint4 g_wih1H[24 * 32], g_wih1L[24 * 32];   // K=16
__device__ uint4 g_whh1H[192 * 32];                    // -> SMEM
__device__ uint4 g_wih2H[192 * 32];                    // streamed from L2
__device__ uint4 g_whh2H[192 * 32];                    // -> SMEM

// SMEM byte offsets
#define S_WHH1  0        // whh1 hi frags (98304)
#define S_WHH2  98304    // whh2 hi frags (98304)
#define S_H1HI  196608   // h tiles: 32x128 fp16 swizzled (8192 each)
#define S_H1LO  204800
#define S_H2HI  212992
#define S_H2LO  221184
#define S_XHI   229376   // x tiles: 32x16 fp16 (1024 each)
#define S_XLO   230400
#define SMEM_SZ 231424

__device__ __forceinline__ uint32_t smem_u32(const void* p) {
    uint32_t a;
    asm("{ .reg .u64 t; cvta.to.shared.u64 t, %1; cvt.u32.u64 %0, t; }"
        : "=r"(a) : "l"(p));
    return a;
}
__device__ __forceinline__ void ldm2(uint32_t& r0, uint32_t& r1, uint32_t a) {
    asm volatile("ldmatrix.sync.aligned.m8n8.x2.shared.b16 {%0,%1}, [%2];"
                 : "=r"(r0), "=r"(r1) : "r"(a));
}
__device__ __forceinline__ void mmaf(float* d, const uint4& a,
                                     uint32_t b0, uint32_t b1) {
    asm volatile("mma.sync.aligned.m16n8k16.row.col.f32.f16.f16.f32 "
                 "{%0,%1,%2,%3}, {%4,%5,%6,%7}, {%8,%9}, {%0,%1,%2,%3};"
                 : "+f"(d[0]), "+f"(d[1]), "+f"(d[2]), "+f"(d[3])
                 : "r"(a.x), "r"(a.y), "r"(a.z), "r"(a.w), "r"(b0), "r"(b1));
}
__device__ __forceinline__ float sigf(float v) { return 1.f / (1.f + __expf(-v)); }
__device__ __forceinline__ float tanhf_fast(float v) {
    v = fminf(fmaxf(v, -15.f), 15.f);
    float e = __expf(2.f * v);
    return (e - 1.f) / (e + 1.f);
}

// ---- prep: pack fp32 weights into per-lane A fragments --------------------
__global__ void prep_kernel(const float* __restrict__ w_ih1,
                            const float* __restrict__ w_hh1,
                            const float* __restrict__ w_ih2,
                            const float* __restrict__ w_hh2) {
    int t = blockIdx.x * blockDim.x + threadIdx.x;
    if (t >= 600 * 32) return;
    int f = t >> 5, lane = t & 31;
    const float* W; uint4* dh; uint4* dl = nullptr; int K, fl;
    if (f < 24)       { W = w_ih1; dh = g_wih1H; dl = g_wih1L; K = 16;  fl = f; }
    else if (f < 216) { W = w_hh1; dh = g_whh1H; K = 128; fl = f - 24; }
    else if (f < 408) { W = w_ih2; dh = g_wih2H; K = 128; fl = f - 216; }
    else              { W = w_hh2; dh = g_whh2H; K = 128; fl = f - 408; }
    int nkt = K >> 4;
    int mt = fl / nkt, kt = fl % nkt;
    int gid = lane >> 2, tig = lane & 3;
    int r0 = mt * 16 + gid, r1 = r0 + 8, c0 = kt * 16 + tig * 2;
    float2 v[4];
    v[0] = *(const float2*)(W + r0 * K + c0);
    v[1] = *(const float2*)(W + r1 * K + c0);
    v[2] = *(const float2*)(W + r0 * K + c0 + 8);
    v[3] = *(const float2*)(W + r1 * K + c0 + 8);
    uint4 oh, ol;
    uint32_t* ph = (uint32_t*)&oh;
    uint32_t* pl = (uint32_t*)&ol;
#pragma unroll
    for (int q = 0; q < 4; q++) {
        __half2 hi = __floats2half2_rn(v[q].x, v[q].y);
        __half2 lo = __floats2half2_rn(v[q].x - __half2float(__low2half(hi)),
                                       v[q].y - __half2float(__high2half(hi)));
        ph[q] = *(uint32_t*)&hi;
        pl[q] = *(uint32_t*)&lo;
    }
    dh[fl * 32 + lane] = oh;
    if (dl) dl[fl * 32 + lane] = ol;
}

// ---------------------------------------------------------------------------
__global__ __launch_bounds__(NTHR, 1)
void gru_mma_kernel(const float* __restrict__ x,
                    const float* __restrict__ b_ih1, const float* __restrict__ b_hh1,
                    const float* __restrict__ b_ih2, const float* __restrict__ b_hh2,
                    const float* __restrict__ fc_w,  const float* __restrict__ fc_b,
                    float* __restrict__ out) {
    extern __shared__ char smem[];
    const uint32_t sb = smem_u32(smem);
    const int tid = threadIdx.x;
    const int wid = tid >> 5, lane = tid & 31;
    const int wpair = wid & 7;           // gate row-group (rows 16*wpair)
    const int shalf = wid >> 3;          // sample half (samples 16*shalf..)
    const int b0 = blockIdx.x * MB;
    const int gid = lane >> 2, tig = lane & 3;
    const int lr = lane & 7, lh = (lane >> 3) & 1;
    const int xorv = lr << 4;
    const int wbase = wpair * 16;
    const int ntb = shalf * 2;           // this warp's two n-tiles
    const int barid = 1 + shalf;
    const int ht = tid & 255;            // thread index within half

#define BARH() asm volatile("bar.sync %0, 256;" :: "r"(barid) : "memory")

    // ---- init: recurrent weights -> SMEM, zero h tiles, x(0) ----
    {
        uint4* d1 = (uint4*)(smem + S_WHH1);
        uint4* d2 = (uint4*)(smem + S_WHH2);
        for (int i = tid; i < 192 * 32; i += NTHR) {
            d1[i] = g_whh1H[i];
            d2[i] = g_whh2H[i];
        }
        uint4 z4 = make_uint4(0, 0, 0, 0);
        uint4* hz = (uint4*)(smem + S_H1HI);
        for (int i = tid; i < 32768 / 16; i += NTHR) hz[i] = z4;
    }
    if (tid < 256) {
        int m = tid >> 3, p = tid & 7;
        const float2 v = *(const float2*)(x + (size_t)(b0 + m) * 2048 +
                                          (p >> 2) * 1024 + ((2 * p) & 7));
        __half2 hi = __floats2half2_rn(v.x, v.y);
        __half2 lo = __floats2half2_rn(v.x - __half2float(__low2half(hi)),
                                       v.y - __half2float(__high2half(hi)));
        *(__half2*)(smem + S_XHI + m * 32 + p * 4) = hi;
        *(__half2*)(smem + S_XLO + m * 32 + p * 4) = lo;
    }
    // biases (rows j0 = wbase+gid, j1 = j0+8)
    const int j0 = wbase + gid, j1 = j0 + 8;
    float b1r[2] = { b_ih1[j0] + b_hh1[j0],             b_ih1[j1] + b_hh1[j1] };
    float b1z[2] = { b_ih1[128 + j0] + b_hh1[128 + j0], b_ih1[128 + j1] + b_hh1[128 + j1] };
    float b1i[2] = { b_ih1[256 + j0],                   b_ih1[256 + j1] };
    float b1h[2] = { b_hh1[256 + j0],                   b_hh1[256 + j1] };
    float b2r[2] = { b_ih2[j0] + b_hh2[j0],             b_ih2[j1] + b_hh2[j1] };
    float b2z[2] = { b_ih2[128 + j0] + b_hh2[128 + j0], b_ih2[128 + j1] + b_hh2[128 + j1] };
    float b2i[2] = { b_ih2[256 + j0],                   b_ih2[256 + j1] };
    float b2h[2] = { b_hh2[256 + j0],                   b_hh2[256 + j1] };

    float h1reg[8], h2reg[8];
#pragma unroll
    for (int q = 0; q < 8; q++) { h1reg[q] = 0.f; h2reg[q] = 0.f; }

    float ar[2][4], az[2][4], ai[2][4], ah[2][4];
    __syncthreads();

#define ZERO_ACC() { _Pragma("unroll") for (int n_ = 0; n_ < 2; n_++) \
    _Pragma("unroll") for (int e_ = 0; e_ < 4; e_++) { \
        ar[n_][e_] = 0.f; az[n_][e_] = 0.f; ai[n_][e_] = 0.f; ah[n_][e_] = 0.f; } }

// epilogue: gate math + h update + hi/lo store (warp-local)
#define EPILOGUE(br_, bz_, bi_, bh_, hreg_, hiOff_) { \
    _Pragma("unroll") for (int ntl = 0; ntl < 2; ntl++) { \
        int nt_ = ntb + ntl; \
        _Pragma("unroll") for (int e_ = 0; e_ < 4; e_++) { \
            int rowi_ = e_ >> 1; \
            int m_ = nt_ * 8 + tig * 2 + (e_ & 1); \
            float r_ = sigf(ar[ntl][e_] + br_[rowi_]); \
            float z_ = sigf(az[ntl][e_] + bz_[rowi_]); \
            float n_ = tanhf_fast(ai[ntl][e_] + bi_[rowi_] + r_ * (ah[ntl][e_] + bh_[rowi_])); \
            int idx_ = ntl * 4 + e_; \
            float h_ = n_ + z_ * (hreg_[idx_] - n_); \
            hreg_[idx_] = h_; \
            __half hhi_ = __float2half_rn(h_); \
            __half hlo_ = __float2half_rn(h_ - __half2float(hhi_)); \
            int j_ = wbase + gid + rowi_ * 8; \
            int off_ = m_ * 256 + ((2 * j_) ^ ((m_ & 7) << 4)); \
            *(__half*)(smem + hiOff_ + off_) = hhi_; \
            *(__half*)(smem + hiOff_ + 8192 + off_) = hlo_; \
        } } }

    const uint4* wf1 = (const uint4*)(smem + S_WHH1);
    const uint4* wf2 = (const uint4*)(smem + S_WHH2);

#pragma unroll 1
    for (int t = 0; t < LSEQ; t++) {
        ZERO_ACC();
        // ---- L1: x contribution (K=16: Whi*xhi + Whi*xlo + Wlo*xhi) ----
        {
            uint4 Ar = g_wih1H[wpair * 32 + lane];
            uint4 Az = g_wih1H[(8 + wpair) * 32 + lane];
            uint4 Ai = g_wih1H[(16 + wpair) * 32 + lane];
            uint4 Lr = g_wih1L[wpair * 32 + lane];
            uint4 Lz = g_wih1L[(8 + wpair) * 32 + lane];
            uint4 Li = g_wih1L[(16 + wpair) * 32 + lane];
#pragma unroll
            for (int ntl = 0; ntl < 2; ntl++) {
                int nt = ntb + ntl;
                uint32_t a = sb + S_XHI + (nt * 8 + lr) * 32 + lh * 16;
                uint32_t bh0, bh1, bl0, bl1;
                ldm2(bh0, bh1, a);
                ldm2(bl0, bl1, a + 1024);
                mmaf(ar[ntl], Ar, bh0, bh1); mmaf(ar[ntl], Ar, bl0, bl1); mmaf(ar[ntl], Lr, bh0, bh1);
                mmaf(az[ntl], Az, bh0, bh1); mmaf(az[ntl], Az, bl0, bl1); mmaf(az[ntl], Lz, bh0, bh1);
                mmaf(ai[ntl], Ai, bh0, bh1); mmaf(ai[ntl], Ai, bl0, bl1); mmaf(ai[ntl], Li, bh0, bh1);
            }
        }
        // ---- L1: whh1 @ h1 (SMEM-resident frags, h hi+lo) ----
#pragma unroll 2
        for (int kt = 0; kt < 8; kt++) {
            uint4 Ar = wf1[(wpair * 8 + kt) * 32 + lane];
            uint4 Az = wf1[((8 + wpair) * 8 + kt) * 32 + lane];
            uint4 An = wf1[((16 + wpair) * 8 + kt) * 32 + lane];
            uint32_t kb = (uint32_t)((kt * 32 + lh * 16) ^ xorv);
#pragma unroll
            for (int ntl = 0; ntl < 2; ntl++) {
                int nt = ntb + ntl;
                uint32_t a = sb + S_H1HI + (nt * 8 + lr) * 256 + kb;
                uint32_t bh0, bh1, bl0, bl1;
                ldm2(bh0, bh1, a);
                ldm2(bl0, bl1, a + 8192);
                mmaf(ar[ntl], Ar, bh0, bh1); mmaf(ar[ntl], Ar, bl0, bl1);
                mmaf(az[ntl], Az, bh0, bh1); mmaf(az[ntl], Az, bl0, bl1);
                mmaf(ah[ntl], An, bh0, bh1); mmaf(ah[ntl], An, bl0, bl1);
            }
        }
        BARH();                                // half: h1/x reads done
        EPILOGUE(b1r, b1z, b1i, b1h, h1reg, S_H1HI);
        if (ht < 128 && t + 1 < LSEQ) {        // stage x(t+1), own-half rows
            int m = shalf * 16 + (ht >> 3), p = ht & 7;
            const float2 v = *(const float2*)(x + (size_t)(b0 + m) * 2048 +
                                              (p >> 2) * 1024 + (t + 1) * 8 + ((2 * p) & 7));
            __half2 hi = __floats2half2_rn(v.x, v.y);
            __half2 lo = __floats2half2_rn(v.x - __half2float(__low2half(hi)),
                                           v.y - __half2float(__high2half(hi)));
            *(__half2*)(smem + S_XHI + m * 32 + p * 4) = hi;
            *(__half2*)(smem + S_XLO + m * 32 + p * 4) = lo;
        }
        BARH();                                // half: h1(t), x(t+1) visible

        // ---- L2 ----
        ZERO_ACC();
        // wih2 @ h1 (frags streamed from L2)
#pragma unroll 2
        for (int kt = 0; kt < 8; kt++) {
            uint4 Ar = g_wih2H[(wpair * 8 + kt) * 32 + lane];
            uint4 Az = g_wih2H[((8 + wpair) * 8 + kt) * 32 + lane];
            uint4 Ai = g_wih2H[((16 + wpair) * 8 + kt) * 32 + lane];
            uint32_t kb = (uint32_t)((kt * 32 + lh * 16) ^ xorv);
#pragma unroll
            for (int ntl = 0; ntl < 2; ntl++) {
                int nt = ntb + ntl;
                uint32_t a = sb + S_H1HI + (nt * 8 + lr) * 256 + kb;
                uint32_t bh0, bh1, bl0, bl1;
                ldm2(bh0, bh1, a);
                ldm2(bl0, bl1, a + 8192);
                mmaf(ar[ntl], Ar, bh0, bh1); mmaf(ar[ntl], Ar, bl0, bl1);
                mmaf(az[ntl], Az, bh0, bh1); mmaf(az[ntl], Az, bl0, bl1);
                mmaf(ai[ntl], Ai, bh0, bh1); mmaf(ai[ntl], Ai, bl0, bl1);
            }
        }
        // whh2 @ h2 (SMEM-resident frags)
#pragma unroll 2
        for (int kt = 0; kt < 8; kt++) {
            uint4 Ar = wf2[(wpair * 8 + kt) * 32 + lane];
            uint4 Az = wf2[((8 + wpair) * 8 + kt) * 32 + lane];
            uint4 An = wf2[((16 + wpair) * 8 + kt) * 32 + lane];
            uint32_t kb = (uint32_t)((kt * 32 + lh * 16) ^ xorv);
#pragma unroll
            for (int ntl = 0; ntl < 2; ntl++) {
                int nt = ntb + ntl;
                uint32_t a = sb + S_H2HI + (nt * 8 + lr) * 256 + kb;
                uint32_t bh0, bh1, bl0, bl1;
                ldm2(bh0, bh1, a);
                ldm2(bl0, bl1, a + 8192);
                mmaf(ar[ntl], Ar, bh0, bh1); mmaf(ar[ntl], Ar, bl0, bl1);
                mmaf(az[ntl], Az, bh0, bh1); mmaf(az[ntl], Az, bl0, bl1);
                mmaf(ah[ntl], An, bh0, bh1); mmaf(ah[ntl], An, bl0, bl1);
            }
        }
        BARH();                                // half: h1/h2 reads done
        EPILOGUE(b2r, b2z, b2i, b2h, h2reg, S_H2HI);
        // next L1 reads h1/x only (stable since barrier 2) — no barrier needed
    }

    // ---- FC head ----
    __syncthreads();                           // full CTA: weight SMEM now free
    float* hs = (float*)smem;                  // [32][128] fp32
#pragma unroll
    for (int ntl = 0; ntl < 2; ntl++)
#pragma unroll
        for (int e = 0; e < 4; e++) {
            int m = (ntb + ntl) * 8 + tig * 2 + (e & 1);
            int j = wbase + gid + (e >> 1) * 8;
            hs[m * 128 + j] = h2reg[ntl * 4 + e];
        }
    __syncthreads();
    if (tid < 256) {
        int o0 = tid * 3;
#pragma unroll
        for (int o = o0; o < o0 + 3; o++) {
            int m = o / NCLS, c = o - (o / NCLS) * NCLS;
            float acc = fc_b[c];
#pragma unroll 4
            for (int k = 0; k < HID; k++)
                acc = fmaf(fc_w[c * HID + k], hs[m * 128 + k], acc);
            out[(size_t)(b0 + m) * NCLS + c] = acc;
        }
    }
#undef BARH
#undef ZERO_ACC
#undef EPILOGUE
}

// ---------------------------------------------------------------------------
extern "C" void kernel_launch(void* const* d_in, const int* in_sizes, int n_in,
                              void* d_out, int out_size) {
    const float* x     = (const float*)d_in[0];
    const float* w_ih1 = (const float*)d_in[1];
    const float* w_hh1 = (const float*)d_in[2];
    const float* b_ih1 = (const float*)d_in[3];
    const float* b_hh1 = (const float*)d_in[4];
    const float* w_ih2 = (const float*)d_in[5];
    const float* w_hh2 = (const float*)d_in[6];
    const float* b_ih2 = (const float*)d_in[7];
    const float* b_hh2 = (const float*)d_in[8];
    const float* fc_w  = (const float*)d_in[9];
    const float* fc_b  = (const float*)d_in[10];
    float* out = (float*)d_out;

    cudaFuncSetAttribute(gru_mma_kernel,
                         cudaFuncAttributeMaxDynamicSharedMemorySize, SMEM_SZ);

    prep_kernel<<<75, 256>>>(w_ih1, w_hh1, w_ih2, w_hh2);
    gru_mma_kernel<<<4096 / MB, NTHR, SMEM_SZ>>>(x, b_ih1, b_hh1, b_ih2, b_hh2,
                                                 fc_w, fc_b, out);
}